// round 1
// baseline (speedup 1.0000x reference)
#include <cuda_runtime.h>
#include <cuda_bf16.h>
#include <cstdint>

// Problem constants
#define BB 64
#define SS 512
#define HH 768
#define KK 21

// ---------------------------------------------------------------------------
// packed fp32x2 FMA (Blackwell): 2 MACs per instruction
// ---------------------------------------------------------------------------
__device__ __forceinline__ void fma2(unsigned long long& acc,
                                     unsigned long long a,
                                     unsigned long long b) {
    asm("fma.rn.f32x2 %0, %1, %2, %0;" : "+l"(acc) : "l"(a), "l"(b));
}
__device__ __forceinline__ float2 unpack2(unsigned long long v) {
    float lo, hi;
    asm("mov.b64 {%0,%1}, %2;" : "=f"(lo), "=f"(hi) : "l"(v));
    return make_float2(lo, hi);
}

// ---------------------------------------------------------------------------
// Kernel 1: logits[r][c] = hidden[r][:] . W[:][c] + b[c]
//   grid 256 blocks x 128 threads, each block owns 128 rows.
//   W packed in shared as float4 {W[2p][c0],W[2p+1][c0],W[2p][c1],W[2p+1][c1]}
//   hidden staged through shared in 32-wide k chunks (coalesced LDG).
// ---------------------------------------------------------------------------
#define ROWS_PB   128
#define KCHUNK    32
#define NCHUNKS   (HH / KCHUNK)   // 24
#define NPAIRS    (HH / 2)        // 384 k-pairs
#define CPAIRS    11              // col pairs (21 cols padded to 22)
#define SH_STRIDE 34              // 32 + 2 pad (even => 8B-aligned pairs)

// dynamic smem layout:
//   float4 wq [NPAIRS*CPAIRS]            (67584 B)
//   float  sh [ROWS_PB*SH_STRIDE]        (17408 B)
//   float  bias[22]                      (   88 B)
#define SMEM_BYTES (NPAIRS*CPAIRS*16 + ROWS_PB*SH_STRIDE*4 + 22*4)

__global__ __launch_bounds__(ROWS_PB) void gemm_kernel(
    const float* __restrict__ hidden,
    const float* __restrict__ Wg,
    const float* __restrict__ bg,
    float* __restrict__ out) {
    extern __shared__ float smem[];
    float4* wq   = (float4*)smem;
    float*  sh   = smem + NPAIRS * CPAIRS * 4;
    float*  bias = sh + ROWS_PB * SH_STRIDE;

    const int tid  = threadIdx.x;
    const int warp = tid >> 5;
    const int lane = tid & 31;
    const int rowBase = blockIdx.x * ROWS_PB;

    // --- prep: pack W into shared, transposed & paired ---
    for (int idx = tid; idx < NPAIRS * CPAIRS; idx += ROWS_PB) {
        int p  = idx / CPAIRS;
        int cc = idx - p * CPAIRS;
        int c0 = 2 * cc, c1 = c0 + 1;
        float a = Wg[(2 * p)     * KK + c0];
        float b = Wg[(2 * p + 1) * KK + c0];
        float c = (c1 < KK) ? Wg[(2 * p)     * KK + c1] : 0.f;
        float d = (c1 < KK) ? Wg[(2 * p + 1) * KK + c1] : 0.f;
        wq[idx] = make_float4(a, b, c, d);
    }
    if (tid < 22) bias[tid] = (tid < KK) ? bg[tid] : 0.f;

    unsigned long long acc[2 * CPAIRS];
#pragma unroll
    for (int i = 0; i < 2 * CPAIRS; i++) acc[i] = 0ull;

    const int myrow = tid;  // local row 0..127

    for (int chunk = 0; chunk < NCHUNKS; chunk++) {
        const int k0 = chunk * KCHUNK;
        // stage 128 rows x 32 k into shared (each warp loads 32 rows)
#pragma unroll 4
        for (int r = 0; r < 32; r++) {
            int lr = warp * 32 + r;
            sh[lr * SH_STRIDE + lane] =
                hidden[(size_t)(rowBase + lr) * HH + k0 + lane];
        }
        __syncthreads();

        const int kp0 = chunk * (KCHUNK / 2);
#pragma unroll
        for (int p = 0; p < KCHUNK / 2; p++) {
            unsigned long long h2 =
                *(const unsigned long long*)&sh[myrow * SH_STRIDE + 2 * p];
            const ulonglong2* wrow =
                (const ulonglong2*)&wq[(kp0 + p) * CPAIRS];
#pragma unroll
            for (int cc = 0; cc < CPAIRS - 1; cc++) {
                ulonglong2 w2 = wrow[cc];
                fma2(acc[2 * cc],     h2, w2.x);
                fma2(acc[2 * cc + 1], h2, w2.y);
            }
            {   // last pair: only even column 20 is real
                ulonglong2 w2 = wrow[CPAIRS - 1];
                fma2(acc[2 * (CPAIRS - 1)], h2, w2.x);
            }
        }
        __syncthreads();
    }

    // epilogue: reduce pairs, add bias, transpose through shared for
    // coalesced global stores.
    float res[KK];
#pragma unroll
    for (int c = 0; c < KK; c++) {
        float2 f = unpack2(acc[c]);
        res[c] = f.x + f.y + bias[c];
    }
#pragma unroll
    for (int c = 0; c < KK; c++) sh[tid * KK + c] = res[c];
    __syncthreads();
    const size_t base = (size_t)rowBase * KK;
    for (int i = tid; i < ROWS_PB * KK; i += ROWS_PB) out[base + i] = sh[i];
}

// ---------------------------------------------------------------------------
// Kernel 2: CRF per batch. One warp per batch (64 blocks x 32 threads).
//   Factorized logsumexp: s_j = sum_i exp(alpha_i - c) * exp(T_ij)
//   -> 1 exp + 1 log per lane per step; c refreshed every 8 steps.
// ---------------------------------------------------------------------------
__device__ float g_partial[BB];

__global__ void crf_kernel(const float* __restrict__ logits,
                           const int*   __restrict__ labels,
                           const void*  __restrict__ maskraw,
                           const float* __restrict__ start_t,
                           const float* __restrict__ trans,
                           const float* __restrict__ end_t) {
    const int b = blockIdx.x;
    const int lane = threadIdx.x;
    const unsigned FULL = 0xffffffffu;
    const float NEG = -1e30f;

    // per-lane column of exp(trans)
    float tE[KK];
    {
        int j = (lane < KK) ? lane : 0;
#pragma unroll
        for (int i = 0; i < KK; i++) tE[i] = __expf(trans[i * KK + j]);
    }

    // --- sequence length (mask dtype probe: int32 vs packed bytes) ---
    const int* im = (const int*)maskraw;
    bool packed = (im[0] != 1);  // mask[0][0] is true; 1 => int32, 0x01010101 => bytes
    int len = 0;
    if (!packed) {
        const int* m = im + b * SS;
        for (int t = lane; t < SS; t += 32) len += (m[t] != 0);
    } else {
        const unsigned char* m = (const unsigned char*)maskraw + b * SS;
        for (int t = lane; t < SS; t += 32) len += (m[t] != 0);
    }
#pragma unroll
    for (int o = 16; o; o >>= 1) len += __shfl_xor_sync(FULL, len, o);

    const int*   lab = labels + b * SS;
    const float* lg  = logits + (size_t)b * SS * KK;

    // --- numerator (gold path score) ---
    float num = 0.f;
    for (int t = lane; t < len; t += 32) {
        int lt = lab[t];
        float e = lg[t * KK + lt];
        num += (t == 0) ? (start_t[lt] + e) : (e + trans[lab[t - 1] * KK + lt]);
    }
#pragma unroll
    for (int o = 16; o; o >>= 1) num += __shfl_xor_sync(FULL, num, o);

    // --- forward recursion ---
    float alpha = (lane < KK) ? (start_t[lane] + lg[lane]) : NEG;
    float c = __shfl_sync(FULL, alpha, 0);
    for (int t = 1; t < len; t++) {
        if ((t & 7) == 1) c = __shfl_sync(FULL, alpha, 0);  // refresh bound
        float u = __expf(alpha - c);  // lanes >= KK: exp(-huge) = 0
        float em = (lane < KK) ? lg[t * KK + lane] : 0.f;
        float s0 = 0.f, s1 = 0.f, s2 = 0.f;
#pragma unroll
        for (int i = 0; i < KK; i += 3) {
            float u0 = __shfl_sync(FULL, u, i);
            float u1 = __shfl_sync(FULL, u, i + 1);
            float u2 = __shfl_sync(FULL, u, i + 2);
            s0 = fmaf(u0, tE[i],     s0);
            s1 = fmaf(u1, tE[i + 1], s1);
            s2 = fmaf(u2, tE[i + 2], s2);
        }
        float s = (s0 + s1) + s2;
        float na = em + c + __logf(s);
        alpha = (lane < KK) ? na : NEG;
    }

    // --- logZ ---
    float v = (lane < KK) ? (alpha + end_t[lane]) : NEG;
    float m = v;
#pragma unroll
    for (int o = 16; o; o >>= 1) m = fmaxf(m, __shfl_xor_sync(FULL, m, o));
    float e = __expf(v - m);
#pragma unroll
    for (int o = 16; o; o >>= 1) e += __shfl_xor_sync(FULL, e, o);
    float logZ = m + __logf(e);

    if (lane == 0) g_partial[b] = logZ - (num + end_t[lab[len - 1]]);
}

// ---------------------------------------------------------------------------
// Kernel 3: deterministic reduction of 64 partials -> nll scalar
// ---------------------------------------------------------------------------
__global__ void finalize_kernel(float* __restrict__ out_nll) {
    const int t = threadIdx.x;  // 64 threads
    float v = g_partial[t];
#pragma unroll
    for (int o = 16; o; o >>= 1) v += __shfl_xor_sync(0xffffffffu, v, o);
    __shared__ float w2[2];
    if ((t & 31) == 0) w2[t >> 5] = v;
    __syncthreads();
    if (t == 0) out_nll[0] = w2[0] + w2[1];
}

// ---------------------------------------------------------------------------
extern "C" void kernel_launch(void* const* d_in, const int* in_sizes, int n_in,
                              void* d_out, int out_size) {
    const float* hidden  = (const float*)d_in[0];
    const float* W       = (const float*)d_in[1];
    const float* b       = (const float*)d_in[2];
    const float* start_t = (const float*)d_in[3];
    const float* trans   = (const float*)d_in[4];
    const float* end_t   = (const float*)d_in[5];
    const int*   labels  = (const int*)d_in[6];
    const void*  mask    = (const void*)d_in[7];

    float* out     = (float*)d_out;
    float* out_nll = out + (out_size - 1);

    cudaFuncSetAttribute(gemm_kernel,
                         cudaFuncAttributeMaxDynamicSharedMemorySize,
                         SMEM_BYTES);

    gemm_kernel<<<(BB * SS) / ROWS_PB, ROWS_PB, SMEM_BYTES>>>(hidden, W, b, out);
    crf_kernel<<<BB, 32>>>(out, labels, mask, start_t, trans, end_t);
    finalize_kernel<<<1, BB>>>(out_nll);
}

// round 2
// speedup vs baseline: 1.5384x; 1.5384x over previous
#include <cuda_runtime.h>
#include <cstdint>

#define BB 64
#define SS 512
#define HH 768
#define KK 21
#define FULLMASK 0xffffffffu

// ---------------------------------------------------------------------------
// helpers: packed fp32x2 FMA (2 MACs/inst)
// ---------------------------------------------------------------------------
__device__ __forceinline__ void fma2(unsigned long long& acc,
                                     unsigned long long a,
                                     unsigned long long b) {
    asm("fma.rn.f32x2 %0, %1, %2, %0;" : "+l"(acc) : "l"(a), "l"(b));
}
__device__ __forceinline__ float2 unpack2(unsigned long long v) {
    float lo, hi;
    asm("mov.b64 {%0,%1}, %2;" : "=f"(lo), "=f"(hi) : "l"(v));
    return make_float2(lo, hi);
}

// packed W: [384 k-pairs][11 col-pairs] of {W[2p][c0],W[2p+1][c0],W[2p][c1],W[2p+1][c1]}
__device__ float4 g_wpack[384 * 11];
__device__ float  g_partial[BB];

// ---------------------------------------------------------------------------
// Kernel 0: pack W once (coalesced consumers later)
// ---------------------------------------------------------------------------
__global__ void pack_w_kernel(const float* __restrict__ Wg) {
    int idx = blockIdx.x * blockDim.x + threadIdx.x;
    if (idx >= 384 * 11) return;
    int p = idx / 11, cc = idx - p * 11;
    int c0 = 2 * cc, c1 = c0 + 1;
    float a = Wg[(2 * p)     * KK + c0];
    float b = Wg[(2 * p + 1) * KK + c0];
    float c = (c1 < KK) ? Wg[(2 * p)     * KK + c1] : 0.f;
    float d = (c1 < KK) ? Wg[(2 * p + 1) * KK + c1] : 0.f;
    g_wpack[idx] = make_float4(a, b, c, d);
}

// ---------------------------------------------------------------------------
// Kernel 1: GEMM. 512 blocks x 128 threads, 64 rows/block, split-K x2.
//   Double-buffered smem (hidden chunk 64x64 + W chunk), register prefetch.
// ---------------------------------------------------------------------------
#define GT       128
#define GR       64            // rows per block
#define GSTRIDE  66            // 64 k + 2 pad floats
#define WCH      352           // 32 k-pairs * 11 col-pairs per chunk
#define NCH      12            // 768 / 64

__global__ __launch_bounds__(GT, 4) void gemm_kernel(
    const float* __restrict__ hidden,
    const float* __restrict__ bg,
    float* __restrict__ out) {
    __shared__ float  sh[2][GR * GSTRIDE];
    __shared__ float4 wb[2][WCH];

    const int tid = threadIdx.x;
    const int r = tid >> 1;      // local row
    const int h = tid & 1;       // k-half
    const size_t rowBase = (size_t)blockIdx.x * GR;
    const float2* hg = (const float2*)hidden;

    float2 hreg[16];
    float4 wreg[3];

    auto LOADC = [&](int c) {
#pragma unroll
        for (int j = 0; j < 16; j++) {
            int i = tid + j * GT;
            int row = i >> 5, f2 = i & 31;
            hreg[j] = hg[(rowBase + row) * (HH / 2) + c * 32 + f2];
        }
#pragma unroll
        for (int j = 0; j < 3; j++) {
            int idx = tid + j * GT;
            wreg[j] = (idx < WCH) ? g_wpack[c * WCH + idx]
                                  : make_float4(0.f, 0.f, 0.f, 0.f);
        }
    };
    auto STSC = [&](int buf) {
#pragma unroll
        for (int j = 0; j < 16; j++) {
            int i = tid + j * GT;
            int row = i >> 5, f2 = i & 31;
            *(float2*)&sh[buf][row * GSTRIDE + 2 * f2] = hreg[j];
        }
#pragma unroll
        for (int j = 0; j < 3; j++) {
            int idx = tid + j * GT;
            if (idx < WCH) wb[buf][idx] = wreg[j];
        }
    };

    unsigned long long acc[KK];
#pragma unroll
    for (int i = 0; i < KK; i++) acc[i] = 0ull;

    LOADC(0);
    STSC(0);
    __syncthreads();

    for (int c = 0; c < NCH; c++) {
        if (c + 1 < NCH) LOADC(c + 1);   // prefetch next chunk into regs

        const float* hp = &sh[c & 1][r * GSTRIDE + h * 32];
        const float4* wp = &wb[c & 1][(h * 16) * 11];
#pragma unroll
        for (int p = 0; p < 16; p++) {
            unsigned long long h2 = *(const unsigned long long*)&hp[2 * p];
            const ulonglong2* wrow = (const ulonglong2*)&wp[p * 11];
#pragma unroll
            for (int cc = 0; cc < 10; cc++) {
                ulonglong2 w2 = wrow[cc];
                fma2(acc[2 * cc],     h2, w2.x);
                fma2(acc[2 * cc + 1], h2, w2.y);
            }
            fma2(acc[20], h2, wrow[10].x);   // last real column
        }
        __syncthreads();
        if (c + 1 < NCH) {
            STSC((c + 1) & 1);
            __syncthreads();
        }
    }

    // epilogue: reduce pair + combine k-halves + bias, transpose via smem
#pragma unroll
    for (int cc = 0; cc < KK; cc++) {
        float2 f = unpack2(acc[cc]);
        float v = f.x + f.y;
        v += __shfl_xor_sync(FULLMASK, v, 1);   // combine the two k-halves
        if (h == 0) sh[0][r * KK + cc] = v + bg[cc];
    }
    __syncthreads();
    float* outp = out + rowBase * KK;
    for (int i = tid; i < GR * KK; i += GT) outp[i] = sh[0][i];
}

// ---------------------------------------------------------------------------
// Kernel 2: CRF, one warp per batch. u-space recursion:
//   u_{t+1,j} = exp(em_{t+1,j}) * sum_i u_{t,i} * exp(T_ij)
//   renormalize by warp-max every 8 steps; emissions bulk-prefetched 1 group
//   ahead (hides L2 latency behind 8 steps of chain work).
// ---------------------------------------------------------------------------
__global__ void crf_kernel(const float* __restrict__ logits,
                           const int*   __restrict__ labels,
                           const void*  __restrict__ maskraw,
                           const float* __restrict__ start_t,
                           const float* __restrict__ trans,
                           const float* __restrict__ end_t) {
    const int b = blockIdx.x;
    const int lane = threadIdx.x;
    const int jj = (lane < KK) ? lane : KK - 1;

    float tE[KK];
#pragma unroll
    for (int i = 0; i < KK; i++) tE[i] = __expf(trans[i * KK + jj]);
    const float eEnd = __expf(end_t[jj]);

    // sequence length (mask dtype probe: int32 vs packed bytes)
    const int* im = (const int*)maskraw;
    bool bytes = (im[0] != 1);
    int len = 0;
    if (!bytes) {
        const int* m = im + b * SS;
        for (int t = lane; t < SS; t += 32) len += (m[t] != 0);
    } else {
        const unsigned char* m = (const unsigned char*)maskraw + b * SS;
        for (int t = lane; t < SS; t += 32) len += (m[t] != 0);
    }
#pragma unroll
    for (int o = 16; o; o >>= 1) len += __shfl_xor_sync(FULLMASK, len, o);

    const int*   lab = labels + b * SS;
    const float* lg  = logits + (size_t)b * SS * KK;

    // numerator (gold path score)
    float num = 0.f;
    for (int t = lane; t < len; t += 32) {
        int lt = lab[t];
        float e = lg[t * KK + lt];
        num += (t == 0) ? (start_t[lt] + e) : (e + trans[lab[t - 1] * KK + lt]);
    }
#pragma unroll
    for (int o = 16; o; o >>= 1) num += __shfl_xor_sync(FULLMASK, num, o);

    // init: u = exp(alpha0 - m0)
    float a0 = (lane < KK) ? (start_t[lane] + lg[lane]) : -1e30f;
    float m0 = a0;
#pragma unroll
    for (int o = 16; o; o >>= 1) m0 = fmaxf(m0, __shfl_xor_sync(FULLMASK, m0, o));
    float u = __expf(a0 - m0);
    float logC = m0;

    // group-preloaded forward recursion
    float ev[8];
    int t = 1;
#pragma unroll
    for (int j = 0; j < 8; j++) {
        int idx = t + j; idx = (idx < len) ? idx : len - 1;
        ev[j] = lg[idx * KK + jj];
    }
    while (t < len) {
        int steps = len - t; if (steps > 8) steps = 8;
        float evn[8];
#pragma unroll
        for (int j = 0; j < 8; j++) {          // prefetch next group (MLP 8)
            int idx = t + 8 + j; idx = (idx < len) ? idx : len - 1;
            evn[j] = lg[idx * KK + jj];
        }
        float e0 = __expf(ev[0]);
#pragma unroll
        for (int j = 0; j < 8; j++) {
            if (j < steps) {
                float e1 = __expf(ev[(j + 1) & 7]);   // next step's factor, off-chain
                float s0 = 0.f, s1 = 0.f, s2 = 0.f;
#pragma unroll
                for (int i = 0; i < KK; i += 3) {
                    float u0 = __shfl_sync(FULLMASK, u, i);
                    float u1 = __shfl_sync(FULLMASK, u, i + 1);
                    float u2 = __shfl_sync(FULLMASK, u, i + 2);
                    s0 = fmaf(u0, tE[i],     s0);
                    s1 = fmaf(u1, tE[i + 1], s1);
                    s2 = fmaf(u2, tE[i + 2], s2);
                }
                u = ((s0 + s1) + s2) * e0;
                e0 = e1;
            }
        }
        // renorm (overlaps next-group LDGs in flight)
        float M = u;
#pragma unroll
        for (int o = 16; o; o >>= 1) M = fmaxf(M, __shfl_xor_sync(FULLMASK, M, o));
        u *= __frcp_rn(M);
        logC += __logf(M);
#pragma unroll
        for (int j = 0; j < 8; j++) ev[j] = evn[j];
        t += steps;
    }

    // logZ = logC + log( sum_j u_j * exp(end_j) ) ; mask junk lanes here only
    float v = (lane < KK) ? u * eEnd : 0.f;
#pragma unroll
    for (int o = 16; o; o >>= 1) v += __shfl_xor_sync(FULLMASK, v, o);
    float logZ = logC + __logf(v);

    if (lane == 0) g_partial[b] = logZ - (num + end_t[lab[len - 1]]);
}

// ---------------------------------------------------------------------------
// Kernel 3: deterministic reduction of 64 partials -> nll scalar
// ---------------------------------------------------------------------------
__global__ void finalize_kernel(float* __restrict__ out_nll) {
    const int t = threadIdx.x;  // 64 threads
    float v = g_partial[t];
#pragma unroll
    for (int o = 16; o; o >>= 1) v += __shfl_xor_sync(FULLMASK, v, o);
    __shared__ float w2[2];
    if ((t & 31) == 0) w2[t >> 5] = v;
    __syncthreads();
    if (t == 0) out_nll[0] = w2[0] + w2[1];
}

// ---------------------------------------------------------------------------
extern "C" void kernel_launch(void* const* d_in, const int* in_sizes, int n_in,
                              void* d_out, int out_size) {
    const float* hidden  = (const float*)d_in[0];
    const float* W       = (const float*)d_in[1];
    const float* b       = (const float*)d_in[2];
    const float* start_t = (const float*)d_in[3];
    const float* trans   = (const float*)d_in[4];
    const float* end_t   = (const float*)d_in[5];
    const int*   labels  = (const int*)d_in[6];
    const void*  mask    = (const void*)d_in[7];

    float* out     = (float*)d_out;
    float* out_nll = out + (out_size - 1);

    pack_w_kernel<<<(384 * 11 + 127) / 128, 128>>>(W);
    gemm_kernel<<<(BB * SS) / GR, GT>>>(hidden, b, out);
    crf_kernel<<<BB, 32>>>(out, labels, mask, start_t, trans, end_t);
    finalize_kernel<<<1, BB>>>(out_nll);
}

// round 3
// speedup vs baseline: 1.8208x; 1.1835x over previous
#include <cuda_runtime.h>
#include <cstdint>

#define BB 64
#define SS 512
#define HH 768
#define KK 21
#define FULLMASK 0xffffffffu

// ---------------------------------------------------------------------------
// packed fp32x2 FMA (2 MACs/inst)
// ---------------------------------------------------------------------------
__device__ __forceinline__ void fma2(unsigned long long& acc,
                                     unsigned long long a,
                                     unsigned long long b) {
    asm("fma.rn.f32x2 %0, %1, %2, %0;" : "+l"(acc) : "l"(a), "l"(b));
}
__device__ __forceinline__ float2 unpack2(unsigned long long v) {
    float lo, hi;
    asm("mov.b64 {%0,%1}, %2;" : "=f"(lo), "=f"(hi) : "l"(v));
    return make_float2(lo, hi);
}
__device__ __forceinline__ void cpa8(void* dst, const void* src) {
    uint32_t d = (uint32_t)__cvta_generic_to_shared(dst);
    asm volatile("cp.async.ca.shared.global [%0], [%1], 8;\n" ::"r"(d), "l"(src));
}
__device__ __forceinline__ void cpa16(void* dst, const void* src) {
    uint32_t d = (uint32_t)__cvta_generic_to_shared(dst);
    asm volatile("cp.async.cg.shared.global [%0], [%1], 16;\n" ::"r"(d), "l"(src));
}

// packed W: [384 k-pairs][11 col-pairs] of {W[2p][c0],W[2p+1][c0],W[2p][c1],W[2p+1][c1]}
__device__ float4 g_wpack[384 * 11];
__device__ float  g_partial[BB];

// ---------------------------------------------------------------------------
// Kernel 0: pack W once
// ---------------------------------------------------------------------------
__global__ void pack_w_kernel(const float* __restrict__ Wg) {
    int idx = blockIdx.x * blockDim.x + threadIdx.x;
    if (idx >= 384 * 11) return;
    int p = idx / 11, cc = idx - p * 11;
    int c0 = 2 * cc, c1 = c0 + 1;
    float a = Wg[(2 * p)     * KK + c0];
    float b = Wg[(2 * p + 1) * KK + c0];
    float c = (c1 < KK) ? Wg[(2 * p)     * KK + c1] : 0.f;
    float d = (c1 < KK) ? Wg[(2 * p + 1) * KK + c1] : 0.f;
    g_wpack[idx] = make_float4(a, b, c, d);
}

// ---------------------------------------------------------------------------
// Kernel 1: GEMM. 512 blocks x 128 threads, 64 rows/block, split-K x2.
//   cp.async double buffering (no register prefetch -> no spills).
//   Lane map: r = tid&63 (warp-contiguous rows), h = tid>>6 (k-half).
// ---------------------------------------------------------------------------
#define GT    128
#define GR    64
#define GSTR  66            // 64 k + 2 pad (conflict-free LDS.64 phases)
#define WCH   352           // 32 k-pairs * 11 col-pairs per chunk
#define NCH   12            // 768 / 64

__global__ __launch_bounds__(GT) void gemm_kernel(
    const float* __restrict__ hidden,
    const float* __restrict__ bg,
    float* __restrict__ out) {
    __shared__ float  sh[2][GR * GSTR];
    __shared__ float4 wb[2][WCH];

    const int tid = threadIdx.x;
    const int r = tid & 63;       // local row
    const int h = tid >> 6;       // k-half
    const size_t rowBase = (size_t)blockIdx.x * GR;

    auto LOADC = [&](int c, int buf) {
        const float* hsrc = hidden + rowBase * HH + c * 64;
#pragma unroll
        for (int j = 0; j < 16; j++) {
            int idx = tid + j * GT;         // 2048 8B units
            int row = idx >> 5, u8 = idx & 31;
            cpa8(&sh[buf][row * GSTR + u8 * 2], hsrc + (size_t)row * HH + u8 * 2);
        }
#pragma unroll
        for (int j = 0; j < 3; j++) {
            int idx = tid + j * GT;
            if (idx < WCH) cpa16(&wb[buf][idx], &g_wpack[c * WCH + idx]);
        }
        asm volatile("cp.async.commit_group;\n");
    };

    unsigned long long acc[KK];
#pragma unroll
    for (int i = 0; i < KK; i++) acc[i] = 0ull;

    LOADC(0, 0);
    for (int c = 0; c < NCH; c++) {
        if (c + 1 < NCH) {
            LOADC(c + 1, (c + 1) & 1);
            asm volatile("cp.async.wait_group 1;\n");
        } else {
            asm volatile("cp.async.wait_group 0;\n");
        }
        __syncthreads();

        const float*  hp = &sh[c & 1][r * GSTR + h * 32];
        const float4* wp = &wb[c & 1][(h * 16) * 11];
#pragma unroll
        for (int p = 0; p < 16; p++) {
            unsigned long long h2 = *(const unsigned long long*)&hp[2 * p];
            const ulonglong2* wrow = (const ulonglong2*)&wp[p * 11];
#pragma unroll
            for (int cc = 0; cc < 10; cc++) {
                ulonglong2 w2 = wrow[cc];
                fma2(acc[2 * cc],     h2, w2.x);
                fma2(acc[2 * cc + 1], h2, w2.y);
            }
            fma2(acc[20], h2, wrow[10].x);   // last real column
        }
        __syncthreads();
    }

    // epilogue: reduce (even,odd) pair; combine the two k-halves via smem;
    // add bias; coalesced store via smem transpose.
    float res[KK];
#pragma unroll
    for (int cc = 0; cc < KK; cc++) {
        float2 f = unpack2(acc[cc]);
        res[cc] = f.x + f.y;
    }
    if (h == 1) {
#pragma unroll
        for (int cc = 0; cc < KK; cc++) sh[0][r * 22 + cc] = res[cc];
    }
    __syncthreads();
    if (h == 0) {
#pragma unroll
        for (int cc = 0; cc < KK; cc++)
            sh[1][r * KK + cc] = res[cc] + sh[0][r * 22 + cc] + bg[cc];
    }
    __syncthreads();
    float* outp = out + rowBase * KK;
    for (int i = tid; i < GR * KK; i += GT) outp[i] = sh[1][i];
}

// ---------------------------------------------------------------------------
// Kernel 2: CRF, one warp per batch. u-space recursion with u[0]-renorm.
// ---------------------------------------------------------------------------
__global__ void crf_kernel(const float* __restrict__ logits,
                           const int*   __restrict__ labels,
                           const void*  __restrict__ maskraw,
                           const float* __restrict__ start_t,
                           const float* __restrict__ trans,
                           const float* __restrict__ end_t) {
    const int b = blockIdx.x;
    const int lane = threadIdx.x;
    const int jj = (lane < KK) ? lane : KK - 1;

    float tE[KK];
#pragma unroll
    for (int i = 0; i < KK; i++) tE[i] = __expf(trans[i * KK + jj]);
    const float eEnd = __expf(end_t[jj]);

    // sequence length (mask dtype probe: int32 vs packed bytes)
    const int* im = (const int*)maskraw;
    bool bytes = (im[0] != 1);
    int len = 0;
    if (!bytes) {
        const int* m = im + b * SS;
        for (int t = lane; t < SS; t += 32) len += (m[t] != 0);
    } else {
        const unsigned char* m = (const unsigned char*)maskraw + b * SS;
        for (int t = lane; t < SS; t += 32) len += (m[t] != 0);
    }
#pragma unroll
    for (int o = 16; o; o >>= 1) len += __shfl_xor_sync(FULLMASK, len, o);

    const int*   lab = labels + b * SS;
    const float* lg  = logits + (size_t)b * SS * KK;

    // numerator (gold path score)
    float num = 0.f;
    for (int t = lane; t < len; t += 32) {
        int lt = lab[t];
        float e = lg[t * KK + lt];
        num += (t == 0) ? (start_t[lt] + e) : (e + trans[lab[t - 1] * KK + lt]);
    }
#pragma unroll
    for (int o = 16; o; o >>= 1) num += __shfl_xor_sync(FULLMASK, num, o);

    // init: u = exp(alpha0 - m0)
    float a0 = (lane < KK) ? (start_t[lane] + lg[lane]) : -1e30f;
    float m0 = a0;
#pragma unroll
    for (int o = 16; o; o >>= 1) m0 = fmaxf(m0, __shfl_xor_sync(FULLMASK, m0, o));
    float u = __expf(a0 - m0);
    float logC = m0;

    // forward recursion: groups of 8, emissions prefetched one group ahead
    float ev[8];
    int t = 1;
#pragma unroll
    for (int j = 0; j < 8; j++) {
        int idx = t + j; idx = (idx < len) ? idx : len - 1;
        ev[j] = lg[idx * KK + jj];
    }
    while (t < len) {
        int steps = len - t; if (steps > 8) steps = 8;
        float evn[8];
#pragma unroll
        for (int j = 0; j < 8; j++) {          // prefetch next group (MLP 8)
            int idx = t + 8 + j; idx = (idx < len) ? idx : len - 1;
            evn[j] = lg[idx * KK + jj];
        }
        float e0 = __expf(ev[0]);
#pragma unroll
        for (int j = 0; j < 8; j++) {
            if (j < steps) {
                float e1 = __expf(ev[(j + 1) & 7]);   // off-chain
                float s[7];
#pragma unroll
                for (int i = 0; i < 7; i++) {
                    float u0 = __shfl_sync(FULLMASK, u, 3 * i);
                    float u1 = __shfl_sync(FULLMASK, u, 3 * i + 1);
                    float u2 = __shfl_sync(FULLMASK, u, 3 * i + 2);
                    float p = u0 * tE[3 * i];
                    p = fmaf(u1, tE[3 * i + 1], p);
                    p = fmaf(u2, tE[3 * i + 2], p);
                    s[i] = p;
                }
                float sum = ((s[0] + s[1]) + (s[2] + s[3])) +
                            ((s[4] + s[5]) + s[6]);
                u = sum * e0;
                e0 = e1;
            }
        }
        // cheap renorm: single broadcast of u[0] (state spread bounded by
        // emission spread since transitions are +-0.1)
        float c = __shfl_sync(FULLMASK, u, 0);
        u *= __frcp_rn(c);
        logC += __logf(c);
#pragma unroll
        for (int j = 0; j < 8; j++) ev[j] = evn[j];
        t += steps;
    }

    // logZ = logC + log( sum_j u_j * exp(end_j) )
    float v = (lane < KK) ? u * eEnd : 0.f;
#pragma unroll
    for (int o = 16; o; o >>= 1) v += __shfl_xor_sync(FULLMASK, v, o);
    float logZ = logC + __logf(v);

    if (lane == 0) g_partial[b] = logZ - (num + end_t[lab[len - 1]]);
}

// ---------------------------------------------------------------------------
// Kernel 3: deterministic reduction of 64 partials -> nll scalar
// ---------------------------------------------------------------------------
__global__ void finalize_kernel(float* __restrict__ out_nll) {
    const int t = threadIdx.x;  // 64 threads
    float v = g_partial[t];
#pragma unroll
    for (int o = 16; o; o >>= 1) v += __shfl_xor_sync(FULLMASK, v, o);
    __shared__ float w2[2];
    if ((t & 31) == 0) w2[t >> 5] = v;
    __syncthreads();
    if (t == 0) out_nll[0] = w2[0] + w2[1];
}

// ---------------------------------------------------------------------------
extern "C" void kernel_launch(void* const* d_in, const int* in_sizes, int n_in,
                              void* d_out, int out_size) {
    const float* hidden  = (const float*)d_in[0];
    const float* W       = (const float*)d_in[1];
    const float* b       = (const float*)d_in[2];
    const float* start_t = (const float*)d_in[3];
    const float* trans   = (const float*)d_in[4];
    const float* end_t   = (const float*)d_in[5];
    const int*   labels  = (const int*)d_in[6];
    const void*  mask    = (const void*)d_in[7];

    float* out     = (float*)d_out;
    float* out_nll = out + (out_size - 1);

    pack_w_kernel<<<(384 * 11 + 127) / 128, 128>>>(W);
    gemm_kernel<<<(BB * SS) / GR, GT>>>(hidden, b, out);
    crf_kernel<<<BB, 32>>>(out, labels, mask, start_t, trans, end_t);
    finalize_kernel<<<1, BB>>>(out_nll);
}

// round 4
// speedup vs baseline: 2.7085x; 1.4875x over previous
#include <cuda_runtime.h>
#include <cstdint>

#define BB 64
#define SS 512
#define HH 768
#define KK 21
#define FULLMASK 0xffffffffu
#define LOG21 3.0445224377234229f

// ---------------------------------------------------------------------------
// packed fp32x2 FMA (2 MACs/inst)
// ---------------------------------------------------------------------------
__device__ __forceinline__ void fma2(unsigned long long& acc,
                                     unsigned long long a,
                                     unsigned long long b) {
    asm("fma.rn.f32x2 %0, %1, %2, %0;" : "+l"(acc) : "l"(a), "l"(b));
}
__device__ __forceinline__ float2 unpack2(unsigned long long v) {
    float lo, hi;
    asm("mov.b64 {%0,%1}, %2;" : "=f"(lo), "=f"(hi) : "l"(v));
    return make_float2(lo, hi);
}
__device__ __forceinline__ void cpa8(void* dst, const void* src) {
    uint32_t d = (uint32_t)__cvta_generic_to_shared(dst);
    asm volatile("cp.async.ca.shared.global [%0], [%1], 8;\n" ::"r"(d), "l"(src));
}
__device__ __forceinline__ void cpa16(void* dst, const void* src) {
    uint32_t d = (uint32_t)__cvta_generic_to_shared(dst);
    asm volatile("cp.async.cg.shared.global [%0], [%1], 16;\n" ::"r"(d), "l"(src));
}

__device__ float4 g_wpack[384 * 11];
__device__ float  g_partial[BB];
__device__ int    g_ctr = 0;

// ---------------------------------------------------------------------------
// Kernel 0: pack W once
// ---------------------------------------------------------------------------
__global__ void pack_w_kernel(const float* __restrict__ Wg) {
    int idx = blockIdx.x * blockDim.x + threadIdx.x;
    if (idx >= 384 * 11) return;
    int p = idx / 11, cc = idx - p * 11;
    int c0 = 2 * cc, c1 = c0 + 1;
    float a = Wg[(2 * p)     * KK + c0];
    float b = Wg[(2 * p + 1) * KK + c0];
    float c = (c1 < KK) ? Wg[(2 * p)     * KK + c1] : 0.f;
    float d = (c1 < KK) ? Wg[(2 * p + 1) * KK + c1] : 0.f;
    g_wpack[idx] = make_float4(a, b, c, d);
}

// ---------------------------------------------------------------------------
// Kernel 1: GEMM (unchanged from R3: cp.async double buffer, split-K x2)
// ---------------------------------------------------------------------------
#define GT    128
#define GR    64
#define GSTR  66
#define WCH   352
#define NCH   12

__global__ __launch_bounds__(GT) void gemm_kernel(
    const float* __restrict__ hidden,
    const float* __restrict__ bg,
    float* __restrict__ out) {
    __shared__ float  sh[2][GR * GSTR];
    __shared__ float4 wb[2][WCH];

    const int tid = threadIdx.x;
    const int r = tid & 63;
    const int h = tid >> 6;
    const size_t rowBase = (size_t)blockIdx.x * GR;

    auto LOADC = [&](int c, int buf) {
        const float* hsrc = hidden + rowBase * HH + c * 64;
#pragma unroll
        for (int j = 0; j < 16; j++) {
            int idx = tid + j * GT;
            int row = idx >> 5, u8 = idx & 31;
            cpa8(&sh[buf][row * GSTR + u8 * 2], hsrc + (size_t)row * HH + u8 * 2);
        }
#pragma unroll
        for (int j = 0; j < 3; j++) {
            int idx = tid + j * GT;
            if (idx < WCH) cpa16(&wb[buf][idx], &g_wpack[c * WCH + idx]);
        }
        asm volatile("cp.async.commit_group;\n");
    };

    unsigned long long acc[KK];
#pragma unroll
    for (int i = 0; i < KK; i++) acc[i] = 0ull;

    LOADC(0, 0);
    for (int c = 0; c < NCH; c++) {
        if (c + 1 < NCH) {
            LOADC(c + 1, (c + 1) & 1);
            asm volatile("cp.async.wait_group 1;\n");
        } else {
            asm volatile("cp.async.wait_group 0;\n");
        }
        __syncthreads();

        const float*  hp = &sh[c & 1][r * GSTR + h * 32];
        const float4* wp = &wb[c & 1][(h * 16) * 11];
#pragma unroll
        for (int p = 0; p < 16; p++) {
            unsigned long long h2 = *(const unsigned long long*)&hp[2 * p];
            const ulonglong2* wrow = (const ulonglong2*)&wp[p * 11];
#pragma unroll
            for (int cc = 0; cc < 10; cc++) {
                ulonglong2 w2 = wrow[cc];
                fma2(acc[2 * cc],     h2, w2.x);
                fma2(acc[2 * cc + 1], h2, w2.y);
            }
            fma2(acc[20], h2, wrow[10].x);
        }
        __syncthreads();
    }

    float res[KK];
#pragma unroll
    for (int cc = 0; cc < KK; cc++) {
        float2 f = unpack2(acc[cc]);
        res[cc] = f.x + f.y;
    }
    if (h == 1) {
#pragma unroll
        for (int cc = 0; cc < KK; cc++) sh[0][r * 22 + cc] = res[cc];
    }
    __syncthreads();
    if (h == 0) {
#pragma unroll
        for (int cc = 0; cc < KK; cc++)
            sh[1][r * KK + cc] = res[cc] + sh[0][r * 22 + cc] + bg[cc];
    }
    __syncthreads();
    float* outp = out + rowBase * KK;
    for (int i = tid; i < GR * KK; i += GT) outp[i] = sh[1][i];
}

// ---------------------------------------------------------------------------
// Kernel 2: bidirectional CRF. One block (96 thr) per batch.
//   warp 0: forward alpha to t=m; warp 1: backward beta to t=m;
//   warp 2: numerator. Combine Z = sum_i alpha_m[i]*beta_m[i].
//   tE pre-scaled by 1/21 (logC corrected analytically) -> renorm every 16.
// ---------------------------------------------------------------------------
#define RN 16

__device__ __forceinline__ int seq_len_w(const void* maskraw, int b, int lane) {
    const int* im = (const int*)maskraw;
    bool bytes = (im[0] != 1);
    int len = 0;
    if (!bytes) {
        const int* m = im + b * SS;
        for (int t = lane; t < SS; t += 32) len += (m[t] != 0);
    } else {
        const unsigned char* m = (const unsigned char*)maskraw + b * SS;
        for (int t = lane; t < SS; t += 32) len += (m[t] != 0);
    }
#pragma unroll
    for (int o = 16; o; o >>= 1) len += __shfl_xor_sync(FULLMASK, len, o);
    return len;
}

__global__ __launch_bounds__(96) void crf_kernel(
    const float* __restrict__ logits,
    const int*   __restrict__ labels,
    const void*  __restrict__ maskraw,
    const float* __restrict__ start_t,
    const float* __restrict__ trans,
    const float* __restrict__ end_t,
    float* __restrict__ out_nll) {
    const int b = blockIdx.x;
    const int tid = threadIdx.x;
    const int lane = tid & 31;
    const int w = tid >> 5;
    const int jj = (lane < KK) ? lane : KK - 1;

    __shared__ float s_uf[32], s_ub[32];
    __shared__ float s_cf, s_cb, s_num, s_end;

    const int len = seq_len_w(maskraw, b, lane);
    const int m = len >> 1;                 // fwd steps = m, bwd steps = len-1-m
    const int*   lab = labels + b * SS;
    const float* lg  = logits + (size_t)b * SS * KK;

    if (w == 2) {
        // numerator (gold path score)
        float num = 0.f;
        for (int t = lane; t < len; t += 32) {
            int lt = lab[t];
            float e = lg[t * KK + lt];
            num += (t == 0) ? (start_t[lt] + e)
                            : (e + trans[lab[t - 1] * KK + lt]);
        }
#pragma unroll
        for (int o = 16; o; o >>= 1) num += __shfl_xor_sync(FULLMASK, num, o);
        if (lane == 0) {
            s_num = num;
            s_end = end_t[lab[len - 1]];
        }
    } else if (w == 0) {
        // ---------------- forward: alpha_0 .. alpha_m ----------------
        float tE[KK];
#pragma unroll
        for (int i = 0; i < KK; i++)
            tE[i] = __expf(trans[i * KK + jj]) * (1.f / 21.f);

        float a0 = (lane < KK) ? (start_t[lane] + lg[lane]) : -1e30f;
        float m0 = a0;
#pragma unroll
        for (int o = 16; o; o >>= 1)
            m0 = fmaxf(m0, __shfl_xor_sync(FULLMASK, m0, o));
        float u = __expf(a0 - m0);
        float logC = m0;

        const int nf = m;                   // emissions t=1..m
        float ev[RN], evn[RN];
#pragma unroll
        for (int j = 0; j < RN; j++) {
            int idx = (j < nf) ? j : nf - 1;
            ev[j] = lg[(1 + idx) * KK + jj];
        }
        int pos = 0;
        while (pos < nf) {
            int steps = nf - pos; if (steps > RN) steps = RN;
#pragma unroll
            for (int j = 0; j < RN; j++) {
                int idx = pos + RN + j; idx = (idx < nf) ? idx : nf - 1;
                evn[j] = lg[(1 + idx) * KK + jj];
            }
            float e0 = __expf(ev[0]);
#pragma unroll
            for (int j = 0; j < RN; j++) {
                if (j < steps) {
                    float e1 = __expf(ev[(j + 1) & (RN - 1)]);
                    float s[7];
#pragma unroll
                    for (int i = 0; i < 7; i++) {
                        float u0 = __shfl_sync(FULLMASK, u, 3 * i);
                        float u1 = __shfl_sync(FULLMASK, u, 3 * i + 1);
                        float u2 = __shfl_sync(FULLMASK, u, 3 * i + 2);
                        float p = u0 * tE[3 * i];
                        p = fmaf(u1, tE[3 * i + 1], p);
                        p = fmaf(u2, tE[3 * i + 2], p);
                        s[i] = p;
                    }
                    u = (((s[0] + s[1]) + (s[2] + s[3])) +
                         ((s[4] + s[5]) + s[6])) * e0;
                    e0 = e1;
                }
            }
            float c = __shfl_sync(FULLMASK, u, 0);
            u *= __frcp_rn(c);
            logC += __logf(c);
#pragma unroll
            for (int j = 0; j < RN; j++) ev[j] = evn[j];
            pos += steps;
        }
        s_uf[lane] = u;
        if (lane == 0) s_cf = logC + (float)nf * LOG21;
    } else {
        // ---------------- backward: beta_{len-1} .. beta_m ----------------
        float tEb[KK];                      // row jj of exp(trans)/21
#pragma unroll
        for (int i = 0; i < KK; i++)
            tEb[i] = __expf(trans[jj * KK + i]) * (1.f / 21.f);

        float v = __expf(end_t[jj]);
        float logC = 0.f;

        const int nb = len - 1 - m;         // emissions t=len-1 .. m+1
        float ev[RN], evn[RN];
#pragma unroll
        for (int j = 0; j < RN; j++) {
            int idx = (j < nb) ? j : nb - 1;
            ev[j] = lg[(len - 1 - idx) * KK + jj];
        }
        int pos = 0;
        while (pos < nb) {
            int steps = nb - pos; if (steps > RN) steps = RN;
#pragma unroll
            for (int j = 0; j < RN; j++) {
                int idx = pos + RN + j; idx = (idx < nb) ? idx : nb - 1;
                evn[j] = lg[(len - 1 - idx) * KK + jj];
            }
            float e0 = __expf(ev[0]);
#pragma unroll
            for (int j = 0; j < RN; j++) {
                if (j < steps) {
                    float e1 = __expf(ev[(j + 1) & (RN - 1)]);
                    float wv = v * e0;      // lane's own e_{t+1}[j]*beta[j]
                    float s[7];
#pragma unroll
                    for (int i = 0; i < 7; i++) {
                        float w0 = __shfl_sync(FULLMASK, wv, 3 * i);
                        float w1 = __shfl_sync(FULLMASK, wv, 3 * i + 1);
                        float w2 = __shfl_sync(FULLMASK, wv, 3 * i + 2);
                        float p = w0 * tEb[3 * i];
                        p = fmaf(w1, tEb[3 * i + 1], p);
                        p = fmaf(w2, tEb[3 * i + 2], p);
                        s[i] = p;
                    }
                    v = ((s[0] + s[1]) + (s[2] + s[3])) +
                        ((s[4] + s[5]) + s[6]);
                    e0 = e1;
                }
            }
            float c = __shfl_sync(FULLMASK, v, 0);
            v *= __frcp_rn(c);
            logC += __logf(c);
#pragma unroll
            for (int j = 0; j < RN; j++) ev[j] = evn[j];
            pos += steps;
        }
        s_ub[lane] = v;
        if (lane == 0) s_cb = logC + (float)nb * LOG21;
    }

    __syncthreads();

    if (w == 0) {
        float p = (lane < KK) ? s_uf[lane] * s_ub[lane] : 0.f;
#pragma unroll
        for (int o = 16; o; o >>= 1) p += __shfl_xor_sync(FULLMASK, p, o);
        float logZ = __logf(p) + s_cf + s_cb;
        if (lane == 0) {
            g_partial[b] = logZ - (s_num + s_end);
            __threadfence();
            int old = atomicAdd(&g_ctr, 1);
            if (old == BB - 1) {
                __threadfence();
                float vsum = g_partial[lane] + g_partial[lane + 32];
                // lane==0 only here; gather serially is slow — do it vector:
                // (we are a single thread; loop instead)
                float tot = 0.f;
                for (int i = 0; i < BB; i++) tot += g_partial[i];
                out_nll[0] = tot;
                g_ctr = 0;
            }
        }
    }
}

// ---------------------------------------------------------------------------
extern "C" void kernel_launch(void* const* d_in, const int* in_sizes, int n_in,
                              void* d_out, int out_size) {
    const float* hidden  = (const float*)d_in[0];
    const float* W       = (const float*)d_in[1];
    const float* b       = (const float*)d_in[2];
    const float* start_t = (const float*)d_in[3];
    const float* trans   = (const float*)d_in[4];
    const float* end_t   = (const float*)d_in[5];
    const int*   labels  = (const int*)d_in[6];
    const void*  mask    = (const void*)d_in[7];

    float* out     = (float*)d_out;
    float* out_nll = out + (out_size - 1);

    pack_w_kernel<<<(384 * 11 + 127) / 128, 128>>>(W);
    gemm_kernel<<<(BB * SS) / GR, GT>>>(hidden, b, out);
    crf_kernel<<<BB, 96>>>(out, labels, mask, start_t, trans, end_t, out_nll);
}

// round 5
// speedup vs baseline: 3.5523x; 1.3116x over previous
#include <cuda_runtime.h>
#include <cstdint>

#define BB 64
#define SS 512
#define HH 768
#define KK 21
#define FULLMASK 0xffffffffu
#define LOG21 3.0445224377234229f

// ---------------------------------------------------------------------------
// packed fp32x2 FMA (2 MACs/inst)
// ---------------------------------------------------------------------------
__device__ __forceinline__ void fma2(unsigned long long& acc,
                                     unsigned long long a,
                                     unsigned long long b) {
    asm("fma.rn.f32x2 %0, %1, %2, %0;" : "+l"(acc) : "l"(a), "l"(b));
}
__device__ __forceinline__ float2 unpack2(unsigned long long v) {
    float lo, hi;
    asm("mov.b64 {%0,%1}, %2;" : "=f"(lo), "=f"(hi) : "l"(v));
    return make_float2(lo, hi);
}
__device__ __forceinline__ float rcpa(float x) {
    float r;
    asm("rcp.approx.f32 %0, %1;" : "=f"(r) : "f"(x));
    return r;
}
__device__ __forceinline__ void cpa8(void* dst, const void* src) {
    uint32_t d = (uint32_t)__cvta_generic_to_shared(dst);
    asm volatile("cp.async.ca.shared.global [%0], [%1], 8;\n" ::"r"(d), "l"(src));
}
__device__ __forceinline__ void cpa16(void* dst, const void* src) {
    uint32_t d = (uint32_t)__cvta_generic_to_shared(dst);
    asm volatile("cp.async.cg.shared.global [%0], [%1], 16;\n" ::"r"(d), "l"(src));
}

__device__ float4 g_wpack[384 * 11];
__device__ float  g_partial[BB];
__device__ int    g_ctr = 0;

// ---------------------------------------------------------------------------
// Kernel 0: pack W once
// ---------------------------------------------------------------------------
__global__ void pack_w_kernel(const float* __restrict__ Wg) {
    int idx = blockIdx.x * blockDim.x + threadIdx.x;
    if (idx >= 384 * 11) return;
    int p = idx / 11, cc = idx - p * 11;
    int c0 = 2 * cc, c1 = c0 + 1;
    float a = Wg[(2 * p)     * KK + c0];
    float b = Wg[(2 * p + 1) * KK + c0];
    float c = (c1 < KK) ? Wg[(2 * p)     * KK + c1] : 0.f;
    float d = (c1 < KK) ? Wg[(2 * p + 1) * KK + c1] : 0.f;
    g_wpack[idx] = make_float4(a, b, c, d);
}

// ---------------------------------------------------------------------------
// Kernel 1: GEMM. 256 blocks x 128 threads, 128 rows/block.
//   2 rows per thread (r2, r2+64), split-K x2. cp.async double buffer.
//   Per k-pair: 2 LDS.64 + 11 LDS.128(bcast) feed 42 FFMA2 -> FMA-bound.
// ---------------------------------------------------------------------------
#define GT    128
#define GR    128              // rows per block
#define GSTR  66               // 64 k + 2 pad
#define WCH   352              // 32 k-pairs * 11 col-pairs per chunk
#define NCH   12
#define HFLOATS (GR * GSTR)    // 8448 floats per hidden buffer
// dynamic smem: 2 hidden buffers + 2 W buffers
#define GSMEM (2 * HFLOATS * 4 + 2 * WCH * 16)

__global__ __launch_bounds__(GT) void gemm_kernel(
    const float* __restrict__ hidden,
    const float* __restrict__ bg,
    float* __restrict__ out) {
    extern __shared__ float dsm[];
    float*  shh = dsm;                       // [2][HFLOATS]
    float4* wb  = (float4*)(dsm + 2 * HFLOATS);  // [2][WCH]

    const int tid = threadIdx.x;
    const int r2 = tid & 63;     // thread's first local row; second = r2+64
    const int h = tid >> 6;      // k-half
    const size_t rowBase = (size_t)blockIdx.x * GR;

    auto LOADC = [&](int c, int buf) {
        const float* hsrc = hidden + rowBase * HH + c * 64;
        float* dst = shh + buf * HFLOATS;
#pragma unroll
        for (int j = 0; j < 32; j++) {
            int idx = tid + j * GT;          // 4096 8B units
            int row = idx >> 5, u8 = idx & 31;
            cpa8(&dst[row * GSTR + u8 * 2], hsrc + (size_t)row * HH + u8 * 2);
        }
#pragma unroll
        for (int j = 0; j < 3; j++) {
            int idx = tid + j * GT;
            if (idx < WCH) cpa16(&wb[buf * WCH + idx], &g_wpack[c * WCH + idx]);
        }
        asm volatile("cp.async.commit_group;\n");
    };

    unsigned long long accA[KK], accB[KK];
#pragma unroll
    for (int i = 0; i < KK; i++) { accA[i] = 0ull; accB[i] = 0ull; }

    LOADC(0, 0);
    for (int c = 0; c < NCH; c++) {
        if (c + 1 < NCH) {
            LOADC(c + 1, (c + 1) & 1);
            asm volatile("cp.async.wait_group 1;\n");
        } else {
            asm volatile("cp.async.wait_group 0;\n");
        }
        __syncthreads();

        const float* hpA = &shh[(c & 1) * HFLOATS + r2 * GSTR + h * 32];
        const float* hpB = hpA + 64 * GSTR;
        const float4* wp = &wb[(c & 1) * WCH + (h * 16) * 11];
#pragma unroll
        for (int p = 0; p < 16; p++) {
            unsigned long long h2a = *(const unsigned long long*)&hpA[2 * p];
            unsigned long long h2b = *(const unsigned long long*)&hpB[2 * p];
            const ulonglong2* wrow = (const ulonglong2*)&wp[p * 11];
#pragma unroll
            for (int cc = 0; cc < 10; cc++) {
                ulonglong2 w2 = wrow[cc];
                fma2(accA[2 * cc],     h2a, w2.x);
                fma2(accA[2 * cc + 1], h2a, w2.y);
                fma2(accB[2 * cc],     h2b, w2.x);
                fma2(accB[2 * cc + 1], h2b, w2.y);
            }
            ulonglong2 w2 = wrow[10];
            fma2(accA[20], h2a, w2.x);
            fma2(accB[20], h2b, w2.x);
        }
        __syncthreads();
    }

    // epilogue: reduce pairs; combine k-halves via smem; bias; coalesced store
    float resA[KK], resB[KK];
#pragma unroll
    for (int cc = 0; cc < KK; cc++) {
        float2 fa = unpack2(accA[cc]);
        float2 fb = unpack2(accB[cc]);
        resA[cc] = fa.x + fa.y;
        resB[cc] = fb.x + fb.y;
    }
    // h==1 stores its partials (GR rows x 22 floats = 2816 floats in shh[0])
    if (h == 1) {
#pragma unroll
        for (int cc = 0; cc < KK; cc++) {
            shh[r2 * 22 + cc] = resA[cc];
            shh[(64 + r2) * 22 + cc] = resB[cc];
        }
    }
    __syncthreads();
    float* shOut = shh + GR * 22;            // GR x 21 floats
    if (h == 0) {
#pragma unroll
        for (int cc = 0; cc < KK; cc++) {
            shOut[r2 * KK + cc] = resA[cc] + shh[r2 * 22 + cc] + bg[cc];
            shOut[(64 + r2) * KK + cc] =
                resB[cc] + shh[(64 + r2) * 22 + cc] + bg[cc];
        }
    }
    __syncthreads();
    float* outp = out + rowBase * KK;
#pragma unroll
    for (int j = 0; j < (GR * KK) / GT; j++) outp[tid + j * GT] = shOut[tid + j * GT];
    // GR*KK = 2688 = 21 * 128 exact
}

// ---------------------------------------------------------------------------
// Kernel 2: bidirectional CRF. One block (96 thr) per batch.
//   Branch-free 16-step main groups + serial tail. Fused final reduction.
// ---------------------------------------------------------------------------
#define RN 16

__device__ __forceinline__ int seq_len_w(const void* maskraw, int b, int lane) {
    const int* im = (const int*)maskraw;
    bool bytes = (im[0] != 1);
    int len = 0;
    if (!bytes) {
        const int* m = im + b * SS;
        for (int t = lane; t < SS; t += 32) len += (m[t] != 0);
    } else {
        const unsigned char* m = (const unsigned char*)maskraw + b * SS;
        for (int t = lane; t < SS; t += 32) len += (m[t] != 0);
    }
#pragma unroll
    for (int o = 16; o; o >>= 1) len += __shfl_xor_sync(FULLMASK, len, o);
    return len;
}

// one recursion step: u <- (sum_i shfl(u,i)*tE[i]) * e0
__device__ __forceinline__ float crf_step(float u, const float* tE, float e0) {
    float s[7];
#pragma unroll
    for (int i = 0; i < 7; i++) {
        float u0 = __shfl_sync(FULLMASK, u, 3 * i);
        float u1 = __shfl_sync(FULLMASK, u, 3 * i + 1);
        float u2 = __shfl_sync(FULLMASK, u, 3 * i + 2);
        float p = u0 * tE[3 * i];
        p = fmaf(u1, tE[3 * i + 1], p);
        p = fmaf(u2, tE[3 * i + 2], p);
        s[i] = p;
    }
    return (((s[0] + s[1]) + (s[2] + s[3])) + ((s[4] + s[5]) + s[6])) * e0;
}

// run n steps of the recursion; emission t-index = base + dir*stepIdx
// (stepIdx 0..n-1). Returns updated u; logC accumulated by ref.
__device__ __forceinline__ float crf_run(float u, float& logC, const float* tE,
                                         const float* lg, int jj,
                                         int base, int dir, int n) {
    float ev[RN], evn[RN];
#pragma unroll
    for (int j = 0; j < RN; j++) {
        int idx = (j < n) ? j : n - 1;
        ev[j] = lg[(base + dir * idx) * KK + jj];
    }
    int pos = 0;
    // -------- full groups, branch-free --------
    while (pos + RN <= n) {
#pragma unroll
        for (int j = 0; j < RN; j++) {
            int idx = pos + RN + j; idx = (idx < n) ? idx : n - 1;
            evn[j] = lg[(base + dir * idx) * KK + jj];
        }
        float e0 = __expf(ev[0]);
#pragma unroll
        for (int j = 0; j < RN; j++) {
            float e1 = __expf(ev[(j + 1) & (RN - 1)]);
            u = crf_step(u, tE, e0);
            e0 = e1;
        }
        float c = __shfl_sync(FULLMASK, u, 0);
        u *= rcpa(c);
        logC += __logf(c);
#pragma unroll
        for (int j = 0; j < RN; j++) ev[j] = evn[j];
        pos += RN;
    }
    // -------- tail (< RN steps), executed once --------
    int tail = n - pos;
    for (int j = 0; j < tail; j++) {
        float e0 = __expf(ev[j]);
        u = crf_step(u, tE, e0);
    }
    if (tail) {
        float c = __shfl_sync(FULLMASK, u, 0);
        u *= rcpa(c);
        logC += __logf(c);
    }
    logC += (float)n * LOG21;
    return u;
}

__global__ __launch_bounds__(96) void crf_kernel(
    const float* __restrict__ logits,
    const int*   __restrict__ labels,
    const void*  __restrict__ maskraw,
    const float* __restrict__ start_t,
    const float* __restrict__ trans,
    const float* __restrict__ end_t,
    float* __restrict__ out_nll) {
    const int b = blockIdx.x;
    const int tid = threadIdx.x;
    const int lane = tid & 31;
    const int w = tid >> 5;
    const int jj = (lane < KK) ? lane : KK - 1;

    __shared__ float s_uf[32], s_ub[32];
    __shared__ float s_cf, s_cb, s_num, s_end;

    const int len = seq_len_w(maskraw, b, lane);
    const int m = len >> 1;
    const int*   lab = labels + b * SS;
    const float* lg  = logits + (size_t)b * SS * KK;

    if (w == 2) {
        float num = 0.f;
        for (int t = lane; t < len; t += 32) {
            int lt = lab[t];
            float e = lg[t * KK + lt];
            num += (t == 0) ? (start_t[lt] + e)
                            : (e + trans[lab[t - 1] * KK + lt]);
        }
#pragma unroll
        for (int o = 16; o; o >>= 1) num += __shfl_xor_sync(FULLMASK, num, o);
        if (lane == 0) {
            s_num = num;
            s_end = end_t[lab[len - 1]];
        }
    } else if (w == 0) {
        // forward: alpha_0 .. alpha_m (emissions t = 1..m)
        float tE[KK];
#pragma unroll
        for (int i = 0; i < KK; i++)
            tE[i] = __expf(trans[i * KK + jj]) * (1.f / 21.f);
        float a0 = (lane < KK) ? (start_t[lane] + lg[lane]) : -1e30f;
        float m0 = a0;
#pragma unroll
        for (int o = 16; o; o >>= 1)
            m0 = fmaxf(m0, __shfl_xor_sync(FULLMASK, m0, o));
        float u = __expf(a0 - m0);
        float logC = m0;
        u = crf_run(u, logC, tE, lg, jj, /*base=*/1, /*dir=*/+1, /*n=*/m);
        s_uf[lane] = u;
        if (lane == 0) s_cf = logC;
    } else {
        // backward: beta_{len-1} .. beta_m (emissions t = len-1 .. m+1)
        float tEb[KK];
#pragma unroll
        for (int i = 0; i < KK; i++)
            tEb[i] = __expf(trans[jj * KK + i]) * (1.f / 21.f);
        float v = __expf(end_t[jj]);
        float logC = 0.f;
        v = crf_run(v, logC, tEb, lg, jj, /*base=*/len - 1, /*dir=*/-1,
                    /*n=*/len - 1 - m);
        s_ub[lane] = v;
        if (lane == 0) s_cb = logC;
    }

    __syncthreads();

    if (w == 0) {
        float p = (lane < KK) ? s_uf[lane] * s_ub[lane] : 0.f;
#pragma unroll
        for (int o = 16; o; o >>= 1) p += __shfl_xor_sync(FULLMASK, p, o);
        float logZ = __logf(p) + s_cf + s_cb;
        if (lane == 0) {
            g_partial[b] = logZ - (s_num + s_end);
            __threadfence();
            int old = atomicAdd(&g_ctr, 1);
            if (old == BB - 1) {
                __threadfence();
                float tot = 0.f;
                for (int i = 0; i < BB; i++) tot += g_partial[i];
                out_nll[0] = tot;
                g_ctr = 0;
            }
        }
    }
}

// ---------------------------------------------------------------------------
extern "C" void kernel_launch(void* const* d_in, const int* in_sizes, int n_in,
                              void* d_out, int out_size) {
    const float* hidden  = (const float*)d_in[0];
    const float* W       = (const float*)d_in[1];
    const float* b       = (const float*)d_in[2];
    const float* start_t = (const float*)d_in[3];
    const float* trans   = (const float*)d_in[4];
    const float* end_t   = (const float*)d_in[5];
    const int*   labels  = (const int*)d_in[6];
    const void*  mask    = (const void*)d_in[7];

    float* out     = (float*)d_out;
    float* out_nll = out + (out_size - 1);

    cudaFuncSetAttribute(gemm_kernel,
                         cudaFuncAttributeMaxDynamicSharedMemorySize, GSMEM);

    pack_w_kernel<<<(384 * 11 + 127) / 128, 128>>>(W);
    gemm_kernel<<<(BB * SS) / GR, GT, GSMEM>>>(hidden, b, out);
    crf_kernel<<<BB, 96>>>(out, labels, mask, start_t, trans, end_t, out_nll);
}